// round 9
// baseline (speedup 1.0000x reference)
#include <cuda_runtime.h>

// Problem constants
#define E_      4
#define B_      16384
#define STATE_  29
#define ACT_    8
#define HID_    512

// Tiling
#define TR        32          // batch rows per CTA
#define KT        16          // k-tile staged in SMEM for the 512x512 layer
#define NTHREADS  256
#define HROW      520         // padded SMEM row stride (floats) - kills bank conflicts

typedef unsigned long long u64;

// Scratch (device globals: no allocation allowed in kernel_launch)
__device__ float g_legs_diff[(size_t)E_ * 4 * B_ * 4];        // (E, 4, B, 4)  = 4 MB
__device__ float g_state_out[(size_t)E_ * B_ * STATE_];       // (E, B, 29)    = 7.6 MB

// ---------------- packed fp32x2 helpers (Blackwell) ----------------
__device__ __forceinline__ u64 fma2(u64 a, u64 b, u64 c) {
    u64 d;
    asm("fma.rn.f32x2 %0, %1, %2, %3;" : "=l"(d) : "l"(a), "l"(b), "l"(c));
    return d;
}
__device__ __forceinline__ u64 pack2(float x, float y) {
    u64 r;
    asm("mov.b64 %0, {%1, %2};" : "=l"(r)
        : "r"(__float_as_uint(x)), "r"(__float_as_uint(y)));
    return r;
}
__device__ __forceinline__ void unpack2(u64 v, float& x, float& y) {
    unsigned lo, hi;
    asm("mov.b64 {%0, %1}, %2;" : "=r"(lo), "=r"(hi) : "l"(v));
    x = __uint_as_float(lo);
    y = __uint_as_float(hi);
}

// ---------------- layer 0: IN -> 512, relu, result into Hs ----------------
// Thread (warp wrp, lane) owns rows wrp*4..+3 and float-pairs at cols 2*(lane+32*u).
template <int IN>
__device__ __forceinline__ void dense_in_relu(float* Hs, const float* Xs,
                                              const float* __restrict__ W0,
                                              const float* __restrict__ B0, int t) {
    const int lane = t & 31, wrp = t >> 5;
    const u64* W0v = (const u64*)W0;   // row i starts at i*256 (u64 units)
    const u64* B0v = (const u64*)B0;
#pragma unroll
    for (int r = 0; r < 4; r++) {
        const int row = wrp * 4 + r;
        float xv[IN];
#pragma unroll
        for (int i = 0; i < IN; i++) xv[i] = Xs[row * 32 + i];
#pragma unroll
        for (int u = 0; u < 8; u++) {
            const int cu = lane + 32 * u;            // u64 column index
            u64 a = B0v[cu];                         // start from bias
#pragma unroll
            for (int i = 0; i < IN; i++) {
                u64 w = W0v[(size_t)i * (HID_ / 2) + cu];
                a = fma2(pack2(xv[i], xv[i]), w, a);
            }
            float x, y;
            unpack2(a, x, y);
            *(u64*)&Hs[row * HROW + 2 * cu] = pack2(fmaxf(x, 0.f), fmaxf(y, 0.f));
        }
    }
}

// ---------------- layer 1: 512 -> 512, relu, in-place on Hs ----------------
__device__ __forceinline__ void dense512_relu(float* Hs, float* Ws,
                                              const float* __restrict__ W1,
                                              const float* __restrict__ B1, int t) {
    const int lane = t & 31, wrp = t >> 5;
    u64 acc[4][8];
#pragma unroll
    for (int r = 0; r < 4; r++)
#pragma unroll
        for (int u = 0; u < 8; u++) acc[r][u] = 0ull;

    for (int kt = 0; kt < HID_; kt += KT) {
        __syncthreads();   // protect Ws reuse (also orders Hs writes on entry)
        // stage W1 rows [kt, kt+KT) into SMEM: 8192 floats, 8 float4 per thread
        const float4* src = (const float4*)(W1 + (size_t)kt * HID_);
        float4* dst = (float4*)Ws;
#pragma unroll
        for (int q = 0; q < (KT * HID_ / 4) / NTHREADS; q++)
            dst[q * NTHREADS + t] = src[q * NTHREADS + t];
        __syncthreads();

#pragma unroll
        for (int kk = 0; kk < KT; kk++) {
            const int k = kt + kk;
            float a0 = Hs[(wrp * 4 + 0) * HROW + k];
            float a1 = Hs[(wrp * 4 + 1) * HROW + k];
            float a2 = Hs[(wrp * 4 + 2) * HROW + k];
            float a3 = Hs[(wrp * 4 + 3) * HROW + k];
            u64 p0 = pack2(a0, a0), p1 = pack2(a1, a1);
            u64 p2 = pack2(a2, a2), p3 = pack2(a3, a3);
            const u64* w8 = (const u64*)(Ws + kk * HID_) + lane;  // stride-32 u64 -> conflict-free
#pragma unroll
            for (int u = 0; u < 8; u++) {
                u64 w = w8[u * 32];
                acc[0][u] = fma2(p0, w, acc[0][u]);
                acc[1][u] = fma2(p1, w, acc[1][u]);
                acc[2][u] = fma2(p2, w, acc[2][u]);
                acc[3][u] = fma2(p3, w, acc[3][u]);
            }
        }
    }
    __syncthreads();   // everyone done reading Hs
    // bias + relu + writeback
#pragma unroll
    for (int r = 0; r < 4; r++) {
        const int row = wrp * 4 + r;
#pragma unroll
        for (int u = 0; u < 8; u++) {
            const int c = 2 * lane + 64 * u;
            float x, y;
            unpack2(acc[r][u], x, y);
            x = fmaxf(x + B1[c], 0.f);
            y = fmaxf(y + B1[c + 1], 0.f);
            *(u64*)&Hs[row * HROW + c] = pack2(x, y);
        }
    }
    __syncthreads();
}

// =======================================================================
// Kernel 1: leg MLP over (E, 4B) rows -> g_legs_diff
// =======================================================================
__global__ void __launch_bounds__(NTHREADS, 2)
leg_kernel(const float* __restrict__ state, const float* __restrict__ act,
           const float* __restrict__ wl0, const float* __restrict__ bl0,
           const float* __restrict__ wl1, const float* __restrict__ bl1,
           const float* __restrict__ wl2, const float* __restrict__ bl2,
           const float* __restrict__ mu_leg, const float* __restrict__ sigma_leg,
           const float* __restrict__ mu_t_leg, const float* __restrict__ sigma_t_leg) {
    extern __shared__ float smem[];
    float* Hs = smem;                      // TR * HROW
    float* Ws = smem + TR * HROW;          // KT * HID
    float* Xs = Ws + KT * HID_;            // TR * 32

    const int e = blockIdx.y;
    const int row0 = blockIdx.x * TR;
    const int t = threadIdx.x;

    // build normalized leg inputs: row = j*B + b, feats per reference _leg_inputs
    for (int q = t; q < TR * 6; q += NTHREADS) {
        int r = q / 6, i = q % 6;
        int grow = row0 + r;
        int j = grow >> 14;           // / B_
        int b = grow & (B_ - 1);
        const float* st = state + ((size_t)e * B_ + b) * STATE_;
        const float* ac = act + ((size_t)e * B_ + b) * ACT_;
        float v;
        if (i == 0)      v = st[13 + 2 * j];
        else if (i == 1) v = st[21 + 2 * j];
        else if (i == 2) v = st[14 + 2 * j];
        else if (i == 3) v = st[22 + 2 * j];
        else if (i == 4) v = ac[2 * j];
        else             v = ac[2 * j + 1];
        Xs[r * 32 + i] = (v - mu_leg[i]) / (sigma_leg[i] + 1e-8f);
    }
    __syncthreads();

    dense_in_relu<6>(Hs, Xs, wl0 + (size_t)e * 6 * HID_, bl0 + (size_t)e * HID_, t);
    dense512_relu(Hs, Ws, wl1 + (size_t)e * HID_ * HID_, bl1 + (size_t)e * HID_, t);

    // layer 2: 512 -> 8 (only first 4 outputs kept). Stage wl2 in SMEM.
    const float* W2 = wl2 + (size_t)e * HID_ * 8;
    for (int q = t; q < HID_ * 8; q += NTHREADS) Ws[q] = W2[q];
    __syncthreads();

    const int row = t >> 3, col = t & 7;
    float s = 0.f;
#pragma unroll 8
    for (int k = 0; k < HID_; k++)
        s += Hs[row * HROW + k] * Ws[k * 8 + col];
    s += bl2[e * 8 + col];
    if (col < 4) {
        float d = s * (sigma_t_leg[col] + 1e-8f) + mu_t_leg[col];
        g_legs_diff[((size_t)e * 4 * B_ + row0 + row) * 4 + col] = d;
    }
}

// =======================================================================
// Kernel 2: pose MLP over (E, B) rows -> g_state_out (full 29-dim next state)
// =======================================================================
__global__ void __launch_bounds__(NTHREADS, 2)
pose_kernel(const float* __restrict__ state,
            const float* __restrict__ wp0, const float* __restrict__ bp0,
            const float* __restrict__ wp1, const float* __restrict__ bp1,
            const float* __restrict__ wp2, const float* __restrict__ bp2,
            const float* __restrict__ mu_pose, const float* __restrict__ sigma_pose,
            const float* __restrict__ mu_t_pose, const float* __restrict__ sigma_t_pose) {
    extern __shared__ float smem[];
    float* Hs = smem;
    float* Ws = smem + TR * HROW;
    float* Xs = Ws + KT * HID_;

    const int e = blockIdx.y;
    const int b0 = blockIdx.x * TR;
    const int t = threadIdx.x;

    // pose_in = [state[:13], legs_diff_fmt(16)], normalized
    for (int q = t; q < TR * STATE_; q += NTHREADS) {
        int r = q / STATE_, c = q % STATE_;
        int b = b0 + r;
        float v;
        if (c < 13) {
            v = state[((size_t)e * B_ + b) * STATE_ + c];
        } else {
            int m = c - 13;
            int j, comp;
            if (m < 8) { j = m >> 1; comp = (m & 1) ? 2 : 0; }
            else       { int m2 = m - 8; j = m2 >> 1; comp = (m2 & 1) ? 3 : 1; }
            v = g_legs_diff[((size_t)e * 4 * B_ + (size_t)j * B_ + b) * 4 + comp];
        }
        Xs[r * 32 + c] = (v - mu_pose[c]) / (sigma_pose[c] + 1e-8f);
    }
    __syncthreads();

    dense_in_relu<29>(Hs, Xs, wp0 + (size_t)e * STATE_ * HID_, bp0 + (size_t)e * HID_, t);
    dense512_relu(Hs, Ws, wp1 + (size_t)e * HID_ * HID_, bp1 + (size_t)e * HID_, t);

    // layer 2: 512 -> 26, only cols 0..12 needed. Stage packed [512 x 13].
    const float* W2 = wp2 + (size_t)e * HID_ * 26;
    for (int q = t; q < HID_ * 13; q += NTHREADS) {
        int k = q / 13, c = q % 13;
        Ws[q] = W2[k * 26 + c];
    }
    __syncthreads();

    const int row = t >> 3, col = t & 7;
    const int b = b0 + row;
    const bool two = (col < 5);
    float s0 = 0.f, s1 = 0.f;
#pragma unroll 4
    for (int k = 0; k < HID_; k++) {
        float h = Hs[row * HROW + k];
        s0 += h * Ws[k * 13 + col];
        if (two) s1 += h * Ws[k * 13 + col + 8];
    }
    {
        const float* st = state + ((size_t)e * B_ + b) * STATE_;
        float* o = g_state_out + ((size_t)e * B_ + b) * STATE_;
        float v0 = s0 + bp2[e * 26 + col];
        o[col] = v0 * (sigma_t_pose[col] + 1e-8f) + mu_t_pose[col] + st[col];
        if (two) {
            int c2 = col + 8;
            float v1 = s1 + bp2[e * 26 + c2];
            o[c2] = v1 * (sigma_t_pose[c2] + 1e-8f) + mu_t_pose[c2] + st[c2];
        }
    }

    // leg part of next_state: interleaved curr + diff (cols 13..28)
    if (t < TR) {
        int bb = b0 + t;
        const float* st = state + ((size_t)e * B_ + bb) * STATE_;
        float* o = g_state_out + ((size_t)e * B_ + bb) * STATE_;
#pragma unroll
        for (int j = 0; j < 4; j++) {
            const float* d = g_legs_diff + ((size_t)e * 4 * B_ + (size_t)j * B_ + bb) * 4;
            o[13 + 2 * j] = st[13 + 2 * j] + d[0];
            o[14 + 2 * j] = st[14 + 2 * j] + d[2];
            o[21 + 2 * j] = st[21 + 2 * j] + d[1];
            o[22 + 2 * j] = st[22 + 2 * j] + d[3];
        }
    }
}

// =======================================================================
// Kernel 3: ensemble mean
// =======================================================================
__global__ void mean_kernel(float* __restrict__ out) {
    const size_t n4 = (size_t)B_ * STATE_ / 4;     // 118784 float4s
    const float4* s0 = (const float4*)g_state_out;
    const float4* s1 = (const float4*)(g_state_out + (size_t)1 * B_ * STATE_);
    const float4* s2 = (const float4*)(g_state_out + (size_t)2 * B_ * STATE_);
    const float4* s3 = (const float4*)(g_state_out + (size_t)3 * B_ * STATE_);
    for (size_t i = blockIdx.x * blockDim.x + threadIdx.x; i < n4;
         i += (size_t)gridDim.x * blockDim.x) {
        float4 a = s0[i], b = s1[i], c = s2[i], d = s3[i];
        float4 r;
        r.x = 0.25f * (a.x + b.x + c.x + d.x);
        r.y = 0.25f * (a.y + b.y + c.y + d.y);
        r.z = 0.25f * (a.z + b.z + c.z + d.z);
        r.w = 0.25f * (a.w + b.w + c.w + d.w);
        ((float4*)out)[i] = r;
    }
}

extern "C" void kernel_launch(void* const* d_in, const int* in_sizes, int n_in,
                              void* d_out, int out_size) {
    const float* state      = (const float*)d_in[0];
    const float* act        = (const float*)d_in[1];
    const float* wl0        = (const float*)d_in[2];
    const float* bl0        = (const float*)d_in[3];
    const float* wl1        = (const float*)d_in[4];
    const float* bl1        = (const float*)d_in[5];
    const float* wl2        = (const float*)d_in[6];
    const float* bl2        = (const float*)d_in[7];
    const float* wp0        = (const float*)d_in[8];
    const float* bp0        = (const float*)d_in[9];
    const float* wp1        = (const float*)d_in[10];
    const float* bp1        = (const float*)d_in[11];
    const float* wp2        = (const float*)d_in[12];
    const float* bp2        = (const float*)d_in[13];
    const float* mu_leg     = (const float*)d_in[14];
    const float* sigma_leg  = (const float*)d_in[15];
    const float* mu_pose    = (const float*)d_in[16];
    const float* sigma_pose = (const float*)d_in[17];
    const float* mu_t_leg   = (const float*)d_in[18];
    const float* sigma_t_leg= (const float*)d_in[19];
    const float* mu_t_pose  = (const float*)d_in[20];
    const float* sigma_t_pose=(const float*)d_in[21];

    const int smem = (TR * HROW + KT * HID_ + TR * 32) * (int)sizeof(float);  // ~101 KB
    cudaFuncSetAttribute(leg_kernel, cudaFuncAttributeMaxDynamicSharedMemorySize, smem);
    cudaFuncSetAttribute(pose_kernel, cudaFuncAttributeMaxDynamicSharedMemorySize, smem);

    dim3 g1(4 * B_ / TR, E_);   // 2048 x 4 CTAs
    leg_kernel<<<g1, NTHREADS, smem>>>(state, act, wl0, bl0, wl1, bl1, wl2, bl2,
                                       mu_leg, sigma_leg, mu_t_leg, sigma_t_leg);

    dim3 g2(B_ / TR, E_);       // 512 x 4 CTAs
    pose_kernel<<<g2, NTHREADS, smem>>>(state, wp0, bp0, wp1, bp1, wp2, bp2,
                                        mu_pose, sigma_pose, mu_t_pose, sigma_t_pose);

    mean_kernel<<<256, 256>>>((float*)d_out);
}

// round 10
// speedup vs baseline: 1.0209x; 1.0209x over previous
#include <cuda_runtime.h>

// Problem constants
#define E_      4
#define B_      16384
#define STATE_  29
#define ACT_    8
#define HID_    512

// Tiling
#define TR        32          // batch rows per CTA
#define KT        16          // k-tile staged in SMEM for the 512x512 layer
#define NTHREADS  256
#define HROW      520         // padded SMEM row stride (floats)

typedef unsigned long long u64;

// Scratch (device globals: no allocation allowed in kernel_launch)
__device__ float g_legs_diff[(size_t)E_ * 4 * B_ * 4];        // (E, 4, B, 4)  = 4 MB
__device__ float g_state_out[(size_t)E_ * B_ * STATE_];       // (E, B, 29)    = 7.6 MB

// ---------------- packed fp32x2 helpers (Blackwell) ----------------
__device__ __forceinline__ u64 fma2(u64 a, u64 b, u64 c) {
    u64 d;
    asm("fma.rn.f32x2 %0, %1, %2, %3;" : "=l"(d) : "l"(a), "l"(b), "l"(c));
    return d;
}
__device__ __forceinline__ u64 pack2(float x, float y) {
    u64 r;
    asm("mov.b64 %0, {%1, %2};" : "=l"(r)
        : "r"(__float_as_uint(x)), "r"(__float_as_uint(y)));
    return r;
}
__device__ __forceinline__ void unpack2(u64 v, float& x, float& y) {
    unsigned lo, hi;
    asm("mov.b64 {%0, %1}, %2;" : "=r"(lo), "=r"(hi) : "l"(v));
    x = __uint_as_float(lo);
    y = __uint_as_float(hi);
}

// ---------------- layer 0: IN -> 512, relu, result into Hs ----------------
// Thread (warp wrp, lane) owns rows wrp*4..+3 and float-pairs at cols 2*(lane+32*u).
template <int IN>
__device__ __forceinline__ void dense_in_relu(float* Hs, const float* Xs,
                                              const float* __restrict__ W0,
                                              const float* __restrict__ B0, int t) {
    const int lane = t & 31, wrp = t >> 5;
    const u64* W0v = (const u64*)W0;   // row i starts at i*256 (u64 units)
    const u64* B0v = (const u64*)B0;
#pragma unroll
    for (int r = 0; r < 4; r++) {
        const int row = wrp * 4 + r;
        float xv[IN];
#pragma unroll
        for (int i = 0; i < IN; i++) xv[i] = Xs[row * 32 + i];
#pragma unroll
        for (int u = 0; u < 8; u++) {
            const int cu = lane + 32 * u;            // u64 column index
            u64 a = B0v[cu];                         // start from bias
#pragma unroll
            for (int i = 0; i < IN; i++) {
                u64 w = W0v[(size_t)i * (HID_ / 2) + cu];
                a = fma2(pack2(xv[i], xv[i]), w, a);
            }
            float x, y;
            unpack2(a, x, y);
            *(u64*)&Hs[row * HROW + 2 * cu] = pack2(fmaxf(x, 0.f), fmaxf(y, 0.f));
        }
    }
}

// ---------------- layer 1: 512 -> 512, relu, in-place on Hs ----------------
// Deep M-blocking: each warp owns 8 rows x 256 cols.
//   rg = wrp & 3  -> rows rg*8 .. rg*8+7
//   cg = wrp >> 2 -> u64 columns cg*128 + lane + 32*u, u in 0..3
// Each staged weight u64 is reused across 8 rows (2x fewer LDS bytes/FLOP than
// the 4-row variant), making fma2 issue the binding pipe.
__device__ __forceinline__ void dense512_relu(float* Hs, float* Ws,
                                              const float* __restrict__ W1,
                                              const float* __restrict__ B1, int t) {
    const int lane = t & 31, wrp = t >> 5;
    const int rg = wrp & 3;
    const int cg = wrp >> 2;
    const int row0 = rg * 8;
    const int cu0 = cg * 128 + lane;       // base u64 column

    u64 acc[8][4];
#pragma unroll
    for (int r = 0; r < 8; r++)
#pragma unroll
        for (int u = 0; u < 4; u++) acc[r][u] = 0ull;

    for (int kt = 0; kt < HID_; kt += KT) {
        __syncthreads();   // protect Ws reuse (also orders Hs writes on entry)
        // stage W1 rows [kt, kt+KT) into SMEM: 8192 floats, 8 float4 per thread
        const float4* src = (const float4*)(W1 + (size_t)kt * HID_);
        float4* dst = (float4*)Ws;
#pragma unroll
        for (int q = 0; q < (KT * HID_ / 4) / NTHREADS; q++)
            dst[q * NTHREADS + t] = src[q * NTHREADS + t];
        __syncthreads();

#pragma unroll
        for (int kk = 0; kk < KT; kk++) {
            const int k = kt + kk;
            u64 p[8];
#pragma unroll
            for (int r = 0; r < 8; r++) {
                float a = Hs[(row0 + r) * HROW + k];   // warp-broadcast
                p[r] = pack2(a, a);
            }
            const u64* w4 = (const u64*)(Ws + kk * HID_) + cu0;
#pragma unroll
            for (int u = 0; u < 4; u++) {
                u64 w = w4[u * 32];
#pragma unroll
                for (int r = 0; r < 8; r++)
                    acc[r][u] = fma2(p[r], w, acc[r][u]);
            }
        }
    }
    __syncthreads();   // everyone done reading Hs
    // bias + relu + writeback
#pragma unroll
    for (int r = 0; r < 8; r++) {
        const int row = row0 + r;
#pragma unroll
        for (int u = 0; u < 4; u++) {
            const int c = 2 * (cu0 + 32 * u);
            float x, y;
            unpack2(acc[r][u], x, y);
            x = fmaxf(x + B1[c], 0.f);
            y = fmaxf(y + B1[c + 1], 0.f);
            *(u64*)&Hs[row * HROW + c] = pack2(x, y);
        }
    }
    __syncthreads();
}

// =======================================================================
// Kernel 1: leg MLP over (E, 4B) rows -> g_legs_diff
// =======================================================================
__global__ void __launch_bounds__(NTHREADS, 2)
leg_kernel(const float* __restrict__ state, const float* __restrict__ act,
           const float* __restrict__ wl0, const float* __restrict__ bl0,
           const float* __restrict__ wl1, const float* __restrict__ bl1,
           const float* __restrict__ wl2, const float* __restrict__ bl2,
           const float* __restrict__ mu_leg, const float* __restrict__ sigma_leg,
           const float* __restrict__ mu_t_leg, const float* __restrict__ sigma_t_leg) {
    extern __shared__ float smem[];
    float* Hs = smem;                      // TR * HROW
    float* Ws = smem + TR * HROW;          // KT * HID
    float* Xs = Ws + KT * HID_;            // TR * 32

    const int e = blockIdx.y;
    const int row0 = blockIdx.x * TR;
    const int t = threadIdx.x;

    // build normalized leg inputs: row = j*B + b, feats per reference _leg_inputs
    for (int q = t; q < TR * 6; q += NTHREADS) {
        int r = q / 6, i = q % 6;
        int grow = row0 + r;
        int j = grow >> 14;           // / B_
        int b = grow & (B_ - 1);
        const float* st = state + ((size_t)e * B_ + b) * STATE_;
        const float* ac = act + ((size_t)e * B_ + b) * ACT_;
        float v;
        if (i == 0)      v = st[13 + 2 * j];
        else if (i == 1) v = st[21 + 2 * j];
        else if (i == 2) v = st[14 + 2 * j];
        else if (i == 3) v = st[22 + 2 * j];
        else if (i == 4) v = ac[2 * j];
        else             v = ac[2 * j + 1];
        Xs[r * 32 + i] = (v - mu_leg[i]) / (sigma_leg[i] + 1e-8f);
    }
    __syncthreads();

    dense_in_relu<6>(Hs, Xs, wl0 + (size_t)e * 6 * HID_, bl0 + (size_t)e * HID_, t);
    dense512_relu(Hs, Ws, wl1 + (size_t)e * HID_ * HID_, bl1 + (size_t)e * HID_, t);

    // layer 2: 512 -> 8 (only first 4 outputs kept). Stage wl2 in SMEM.
    const float* W2 = wl2 + (size_t)e * HID_ * 8;
    for (int q = t; q < HID_ * 8; q += NTHREADS) Ws[q] = W2[q];
    __syncthreads();

    const int row = t >> 3, col = t & 7;
    float s = 0.f;
#pragma unroll 8
    for (int k = 0; k < HID_; k++)
        s += Hs[row * HROW + k] * Ws[k * 8 + col];
    s += bl2[e * 8 + col];
    if (col < 4) {
        float d = s * (sigma_t_leg[col] + 1e-8f) + mu_t_leg[col];
        g_legs_diff[((size_t)e * 4 * B_ + row0 + row) * 4 + col] = d;
    }
}

// =======================================================================
// Kernel 2: pose MLP over (E, B) rows -> g_state_out (full 29-dim next state)
// =======================================================================
__global__ void __launch_bounds__(NTHREADS, 2)
pose_kernel(const float* __restrict__ state,
            const float* __restrict__ wp0, const float* __restrict__ bp0,
            const float* __restrict__ wp1, const float* __restrict__ bp1,
            const float* __restrict__ wp2, const float* __restrict__ bp2,
            const float* __restrict__ mu_pose, const float* __restrict__ sigma_pose,
            const float* __restrict__ mu_t_pose, const float* __restrict__ sigma_t_pose) {
    extern __shared__ float smem[];
    float* Hs = smem;
    float* Ws = smem + TR * HROW;
    float* Xs = Ws + KT * HID_;

    const int e = blockIdx.y;
    const int b0 = blockIdx.x * TR;
    const int t = threadIdx.x;

    // pose_in = [state[:13], legs_diff_fmt(16)], normalized
    for (int q = t; q < TR * STATE_; q += NTHREADS) {
        int r = q / STATE_, c = q % STATE_;
        int b = b0 + r;
        float v;
        if (c < 13) {
            v = state[((size_t)e * B_ + b) * STATE_ + c];
        } else {
            int m = c - 13;
            int j, comp;
            if (m < 8) { j = m >> 1; comp = (m & 1) ? 2 : 0; }
            else       { int m2 = m - 8; j = m2 >> 1; comp = (m2 & 1) ? 3 : 1; }
            v = g_legs_diff[((size_t)e * 4 * B_ + (size_t)j * B_ + b) * 4 + comp];
        }
        Xs[r * 32 + c] = (v - mu_pose[c]) / (sigma_pose[c] + 1e-8f);
    }
    __syncthreads();

    dense_in_relu<29>(Hs, Xs, wp0 + (size_t)e * STATE_ * HID_, bp0 + (size_t)e * HID_, t);
    dense512_relu(Hs, Ws, wp1 + (size_t)e * HID_ * HID_, bp1 + (size_t)e * HID_, t);

    // layer 2: 512 -> 26, only cols 0..12 needed. Stage packed [512 x 13].
    const float* W2 = wp2 + (size_t)e * HID_ * 26;
    for (int q = t; q < HID_ * 13; q += NTHREADS) {
        int k = q / 13, c = q % 13;
        Ws[q] = W2[k * 26 + c];
    }
    __syncthreads();

    const int row = t >> 3, col = t & 7;
    const int b = b0 + row;
    const bool two = (col < 5);
    float s0 = 0.f, s1 = 0.f;
#pragma unroll 4
    for (int k = 0; k < HID_; k++) {
        float h = Hs[row * HROW + k];
        s0 += h * Ws[k * 13 + col];
        if (two) s1 += h * Ws[k * 13 + col + 8];
    }
    {
        const float* st = state + ((size_t)e * B_ + b) * STATE_;
        float* o = g_state_out + ((size_t)e * B_ + b) * STATE_;
        float v0 = s0 + bp2[e * 26 + col];
        o[col] = v0 * (sigma_t_pose[col] + 1e-8f) + mu_t_pose[col] + st[col];
        if (two) {
            int c2 = col + 8;
            float v1 = s1 + bp2[e * 26 + c2];
            o[c2] = v1 * (sigma_t_pose[c2] + 1e-8f) + mu_t_pose[c2] + st[c2];
        }
    }

    // leg part of next_state: interleaved curr + diff (cols 13..28)
    if (t < TR) {
        int bb = b0 + t;
        const float* st = state + ((size_t)e * B_ + bb) * STATE_;
        float* o = g_state_out + ((size_t)e * B_ + bb) * STATE_;
#pragma unroll
        for (int j = 0; j < 4; j++) {
            const float* d = g_legs_diff + ((size_t)e * 4 * B_ + (size_t)j * B_ + bb) * 4;
            o[13 + 2 * j] = st[13 + 2 * j] + d[0];
            o[14 + 2 * j] = st[14 + 2 * j] + d[2];
            o[21 + 2 * j] = st[21 + 2 * j] + d[1];
            o[22 + 2 * j] = st[22 + 2 * j] + d[3];
        }
    }
}

// =======================================================================
// Kernel 3: ensemble mean
// =======================================================================
__global__ void mean_kernel(float* __restrict__ out) {
    const size_t n4 = (size_t)B_ * STATE_ / 4;     // 118784 float4s
    const float4* s0 = (const float4*)g_state_out;
    const float4* s1 = (const float4*)(g_state_out + (size_t)1 * B_ * STATE_);
    const float4* s2 = (const float4*)(g_state_out + (size_t)2 * B_ * STATE_);
    const float4* s3 = (const float4*)(g_state_out + (size_t)3 * B_ * STATE_);
    for (size_t i = blockIdx.x * blockDim.x + threadIdx.x; i < n4;
         i += (size_t)gridDim.x * blockDim.x) {
        float4 a = s0[i], b = s1[i], c = s2[i], d = s3[i];
        float4 r;
        r.x = 0.25f * (a.x + b.x + c.x + d.x);
        r.y = 0.25f * (a.y + b.y + c.y + d.y);
        r.z = 0.25f * (a.z + b.z + c.z + d.z);
        r.w = 0.25f * (a.w + b.w + c.w + d.w);
        ((float4*)out)[i] = r;
    }
}

extern "C" void kernel_launch(void* const* d_in, const int* in_sizes, int n_in,
                              void* d_out, int out_size) {
    const float* state      = (const float*)d_in[0];
    const float* act        = (const float*)d_in[1];
    const float* wl0        = (const float*)d_in[2];
    const float* bl0        = (const float*)d_in[3];
    const float* wl1        = (const float*)d_in[4];
    const float* bl1        = (const float*)d_in[5];
    const float* wl2        = (const float*)d_in[6];
    const float* bl2        = (const float*)d_in[7];
    const float* wp0        = (const float*)d_in[8];
    const float* bp0        = (const float*)d_in[9];
    const float* wp1        = (const float*)d_in[10];
    const float* bp1        = (const float*)d_in[11];
    const float* wp2        = (const float*)d_in[12];
    const float* bp2        = (const float*)d_in[13];
    const float* mu_leg     = (const float*)d_in[14];
    const float* sigma_leg  = (const float*)d_in[15];
    const float* mu_pose    = (const float*)d_in[16];
    const float* sigma_pose = (const float*)d_in[17];
    const float* mu_t_leg   = (const float*)d_in[18];
    const float* sigma_t_leg= (const float*)d_in[19];
    const float* mu_t_pose  = (const float*)d_in[20];
    const float* sigma_t_pose=(const float*)d_in[21];

    const int smem = (TR * HROW + KT * HID_ + TR * 32) * (int)sizeof(float);  // ~101 KB
    cudaFuncSetAttribute(leg_kernel, cudaFuncAttributeMaxDynamicSharedMemorySize, smem);
    cudaFuncSetAttribute(pose_kernel, cudaFuncAttributeMaxDynamicSharedMemorySize, smem);

    dim3 g1(4 * B_ / TR, E_);   // 2048 x 4 CTAs
    leg_kernel<<<g1, NTHREADS, smem>>>(state, act, wl0, bl0, wl1, bl1, wl2, bl2,
                                       mu_leg, sigma_leg, mu_t_leg, sigma_t_leg);

    dim3 g2(B_ / TR, E_);       // 512 x 4 CTAs
    pose_kernel<<<g2, NTHREADS, smem>>>(state, wp0, bp0, wp1, bp1, wp2, bp2,
                                        mu_pose, sigma_pose, mu_t_pose, sigma_t_pose);

    mean_kernel<<<256, 256>>>((float*)d_out);
}

// round 12
// speedup vs baseline: 2.1954x; 2.1505x over previous
#include <cuda_runtime.h>
#include <cuda_bf16.h>
#include <cstdint>

// Problem constants
#define E_      4
#define B_      16384
#define STATE_  29
#define HID_    512

// ---------------- SMEM layout (float offsets) ----------------
// A fragments: 32 kc x {mt0,mt1} x 32 lanes x 4 regs (u32) = 8192 u32 = 32KB each
#define OFF_AH  0
#define OFF_AL  8192
#define OFF_R   16384     // phase1: W0s [IN x 512] (<=14848); phase2: Hs [32 x 520]
#define OFF_XS  33024     // 32 x 32
#define OFF_B0  34048     // 512
#define OFF_B1  34560     // 512
#define OFF_W2  35072     // 512 x NO (<=6656)
#define SMEM_FLOATS 41728 // 166912 bytes
#define HROW 520

// ---------------- device scratch ----------------
// Pre-packed W1 fragments: per (net,e): 64 ntiles x 32 kc x 32 lanes x {b0h,b1h,b0l,b1l}
__device__ uint32_t g_B[2][(size_t)E_ * 262144];              // 8 MB total
__device__ float g_legs_diff[(size_t)E_ * 4 * B_ * 4];        // (E, 4, B, 4)
__device__ float g_state_out[(size_t)E_ * B_ * STATE_];       // (E, B, 29)

// ---------------- helpers ----------------
__device__ __forceinline__ uint32_t packbf(float x, float y) {
    __nv_bfloat162 h = __floats2bfloat162_rn(x, y);   // .x = low 16 bits
    return *reinterpret_cast<uint32_t*>(&h);
}
__device__ __forceinline__ float bfhi(float x) {
    return __bfloat162float(__float2bfloat16_rn(x));
}
// mma.sync m16n8k16 row.col f32.bf16.bf16.f32 (standard PTX, sm_80+)
__device__ __forceinline__ void mma16816(float* d, uint4 a, uint32_t b0, uint32_t b1) {
    asm volatile(
        "mma.sync.aligned.m16n8k16.row.col.f32.bf16.bf16.f32 "
        "{%0,%1,%2,%3}, {%4,%5,%6,%7}, {%8,%9}, {%0,%1,%2,%3};"
        : "+f"(d[0]), "+f"(d[1]), "+f"(d[2]), "+f"(d[3])
        : "r"(a.x), "r"(a.y), "r"(a.z), "r"(a.w), "r"(b0), "r"(b1));
}

// =======================================================================
// Prep: split W1 into bf16 hi/lo and pack in mma B-fragment register order.
// Fragment spec (m16n8k16, B col-major): lane l (g=l>>2, c=l&3):
//   b0 = {B[k0+2c][n0+g], B[k0+2c+1][n0+g]},  b1 = {B[k0+2c+8][..], B[k0+2c+9][..]}
// Store per (nt, kc, lane): [b0h, b1h, b0l, b1l]  -> one LDG.128 per consumer.
// =======================================================================
__global__ void prep_kernel(const float* __restrict__ wl1, const float* __restrict__ wp1) {
    int idx = blockIdx.x * 256 + threadIdx.x;      // 524288 total
    int l   = idx & 31;
    int kc  = (idx >> 5) & 31;
    int nt  = (idx >> 10) & 63;
    int e   = (idx >> 16) & 3;
    int net = idx >> 18;
    const float* W = (net ? wp1 : wl1) + (size_t)e * 512 * 512;   // [k][n]
    int g = l >> 2, c = l & 3;
    int n  = nt * 8 + g;
    int k0 = kc * 16 + 2 * c;
    float w00 = W[(size_t)k0 * 512 + n];
    float w01 = W[(size_t)(k0 + 1) * 512 + n];
    float w10 = W[(size_t)(k0 + 8) * 512 + n];
    float w11 = W[(size_t)(k0 + 9) * 512 + n];
    float h00 = bfhi(w00), h01 = bfhi(w01), h10 = bfhi(w10), h11 = bfhi(w11);
    uint32_t* dst = g_B[net] + (size_t)e * 262144 + ((size_t)(nt * 32 + kc) * 32 + l) * 4;
    dst[0] = packbf(w00, w01);
    dst[1] = packbf(w10, w11);
    dst[2] = packbf(w00 - h00, w01 - h01);
    dst[3] = packbf(w10 - h10, w11 - h11);
}

// =======================================================================
// Fused MLP: layer0 (FFMA -> A frags in SMEM) -> layer1 (mma.sync bf16 3x
// split, accumulators in registers) -> relu+b1 -> SMEM -> layer2 (FFMA).
// 32 batch rows per CTA, 256 threads (8 warps; warp w owns n-cols w*64..+63).
// =======================================================================
template <int NET>
__global__ void __launch_bounds__(256, 1)
mlp_kernel(const float* __restrict__ state, const float* __restrict__ act,
           const float* __restrict__ w0, const float* __restrict__ b0v,
           const float* __restrict__ b1v, const float* __restrict__ w2,
           const float* __restrict__ b2v, const float* __restrict__ mu,
           const float* __restrict__ sigma, const float* __restrict__ mu_t,
           const float* __restrict__ sigma_t) {
    constexpr int IN = NET ? 29 : 6;
    constexpr int NO = NET ? 13 : 4;
    extern __shared__ float smem[];
    uint32_t* AH = (uint32_t*)(smem + OFF_AH);
    uint32_t* AL = (uint32_t*)(smem + OFF_AL);
    float* R   = smem + OFF_R;
    float* Xs  = smem + OFF_XS;
    float* B0s = smem + OFF_B0;
    float* B1s = smem + OFF_B1;
    float* W2s = smem + OFF_W2;

    const int t = threadIdx.x, lane = t & 31, wid = t >> 5;
    const int e = blockIdx.y;
    const int row0 = blockIdx.x * 32;

    // ---- stage normalized inputs Xs [32 x 32] ----
    for (int q = t; q < 32 * IN; q += 256) {
        int r = q / IN, i = q % IN;
        float v;
        if (NET == 0) {
            int grow = row0 + r, j = grow >> 14, bb = grow & (B_ - 1);
            const float* st = state + ((size_t)e * B_ + bb) * STATE_;
            const float* ac = act + ((size_t)e * B_ + bb) * 8;
            if (i == 0)      v = st[13 + 2 * j];
            else if (i == 1) v = st[21 + 2 * j];
            else if (i == 2) v = st[14 + 2 * j];
            else if (i == 3) v = st[22 + 2 * j];
            else if (i == 4) v = ac[2 * j];
            else             v = ac[2 * j + 1];
        } else {
            int bb = row0 + r;
            if (i < 13) v = state[((size_t)e * B_ + bb) * STATE_ + i];
            else {
                int m = i - 13, j, comp;
                if (m < 8) { j = m >> 1; comp = (m & 1) ? 2 : 0; }
                else       { int m2 = m - 8; j = m2 >> 1; comp = (m2 & 1) ? 3 : 1; }
                v = g_legs_diff[((size_t)e * 4 * B_ + (size_t)j * B_ + bb) * 4 + comp];
            }
        }
        Xs[r * 32 + i] = (v - mu[i]) / (sigma[i] + 1e-8f);
    }
    // ---- stage W0 [IN x 512] into R, biases, packed W2 ----
    for (int q = t; q < IN * 512; q += 256) R[q] = w0[(size_t)e * IN * 512 + q];
    for (int q = t; q < 512; q += 256) {
        B0s[q] = b0v[(size_t)e * 512 + q];
        B1s[q] = b1v[(size_t)e * 512 + q];
    }
    if (NET == 0) {
        for (int q = t; q < 512 * 4; q += 256) {
            int k = q >> 2, o = q & 3;
            W2s[q] = w2[((size_t)e * 512 + k) * 8 + o];
        }
    } else {
        for (int q = t; q < 512 * 13; q += 256) {
            int k = q / 13, o = q % 13;
            W2s[q] = w2[((size_t)e * 512 + k) * 26 + o];
        }
    }
    __syncthreads();

    // ---- layer0: H[row][k] = relu(X*W0 + b0), written as A fragments ----
    // thread: row = lane, k-phase = wid. Within warp all lanes share cols ->
    // W0s reads are warp-broadcast.
    {
        const int row = lane;
        const int rr = row & 15, mt = row >> 4;
        const int g = rr & 7, rh = rr >> 3;
        const int ln = g * 4 + (wid & 3);
        const int reg = ((wid >> 2) << 1) + rh;
        const int abase = mt * 128 + ln * 4 + reg;
        float xv[IN];
#pragma unroll
        for (int i = 0; i < IN; i++) xv[i] = Xs[row * 32 + i];
#pragma unroll 4
        for (int p = 0; p < 32; p++) {
            const int col0 = p * 16 + 2 * wid;
            float h0 = B0s[col0], h1 = B0s[col0 + 1];
#pragma unroll
            for (int i = 0; i < IN; i++) {
                h0 += xv[i] * R[i * 512 + col0];
                h1 += xv[i] * R[i * 512 + col0 + 1];
            }
            h0 = fmaxf(h0, 0.f);
            h1 = fmaxf(h1, 0.f);
            float h0h = bfhi(h0), h1h = bfhi(h1);
            AH[p * 256 + abase] = packbf(h0, h1);
            AL[p * 256 + abase] = packbf(h0 - h0h, h1 - h1h);
        }
    }
    __syncthreads();

    // ---- layer1: [32 x 512] = A[32 x 512] * W1[512 x 512], 3xbf16 split ----
    float acc[2][8][4];
#pragma unroll
    for (int m = 0; m < 2; m++)
#pragma unroll
        for (int n = 0; n < 8; n++)
#pragma unroll
            for (int j = 0; j < 4; j++) acc[m][n][j] = 0.f;

    const uint32_t* Bb = g_B[NET] + (size_t)e * 262144 + (size_t)wid * 8 * 32 * 128;
    for (int kc = 0; kc < 32; kc++) {
        uint4 ah0 = ((const uint4*)(AH + kc * 256))[lane];
        uint4 ah1 = ((const uint4*)(AH + kc * 256 + 128))[lane];
        uint4 al0 = ((const uint4*)(AL + kc * 256))[lane];
        uint4 al1 = ((const uint4*)(AL + kc * 256 + 128))[lane];
#pragma unroll
        for (int ntl = 0; ntl < 8; ntl++) {
            uint4 vb = *(const uint4*)(Bb + (size_t)ntl * 4096 + kc * 128 + lane * 4);
            mma16816(acc[0][ntl], ah0, vb.x, vb.y);   // Ahi*Bhi
            mma16816(acc[1][ntl], ah1, vb.x, vb.y);
            mma16816(acc[0][ntl], ah0, vb.z, vb.w);   // Ahi*Blo
            mma16816(acc[1][ntl], ah1, vb.z, vb.w);
            mma16816(acc[0][ntl], al0, vb.x, vb.y);   // Alo*Bhi
            mma16816(acc[1][ntl], al1, vb.x, vb.y);
        }
    }

    // ---- epilogue: D + b1, relu -> Hs (overwrites W0s region) ----
    {
        const int g = lane >> 2, c = lane & 3;
#pragma unroll
        for (int mt = 0; mt < 2; mt++) {
#pragma unroll
            for (int ntl = 0; ntl < 8; ntl++) {
                const int col = wid * 64 + ntl * 8 + 2 * c;
                const int r1 = mt * 16 + g, r2 = r1 + 8;
                R[r1 * HROW + col]     = fmaxf(acc[mt][ntl][0] + B1s[col], 0.f);
                R[r1 * HROW + col + 1] = fmaxf(acc[mt][ntl][1] + B1s[col + 1], 0.f);
                R[r2 * HROW + col]     = fmaxf(acc[mt][ntl][2] + B1s[col], 0.f);
                R[r2 * HROW + col + 1] = fmaxf(acc[mt][ntl][3] + B1s[col + 1], 0.f);
            }
        }
    }
    __syncthreads();

    // ---- layer2 + outputs ----
    if (NET == 0) {
        if (t < 128) {
            const int row = t >> 2, o = t & 3;
            float s = 0.f;
#pragma unroll 8
            for (int k = 0; k < 512; k++) s += R[row * HROW + k] * W2s[k * 4 + o];
            float v = s + b2v[(size_t)e * 8 + o];
            g_legs_diff[((size_t)e * 4 * B_ + row0 + row) * 4 + o] =
                v * (sigma_t[o] + 1e-8f) + mu_t[o];
        }
    } else {
        const int row = t >> 3, col = t & 7;
        const int bb = row0 + row;
        const bool two = (col < 5);
        float s0 = 0.f, s1 = 0.f;
#pragma unroll 4
        for (int k = 0; k < 512; k++) {
            float h = R[row * HROW + k];
            s0 += h * W2s[k * 13 + col];
            if (two) s1 += h * W2s[k * 13 + col + 8];
        }
        {
            const float* st = state + ((size_t)e * B_ + bb) * STATE_;
            float* o = g_state_out + ((size_t)e * B_ + bb) * STATE_;
            float v0 = s0 + b2v[(size_t)e * 26 + col];
            o[col] = v0 * (sigma_t[col] + 1e-8f) + mu_t[col] + st[col];
            if (two) {
                int c2 = col + 8;
                float v1 = s1 + b2v[(size_t)e * 26 + c2];
                o[c2] = v1 * (sigma_t[c2] + 1e-8f) + mu_t[c2] + st[c2];
            }
        }
        // leg part of next_state (cols 13..28)
        if (t < 32) {
            int b2i = row0 + t;
            const float* st = state + ((size_t)e * B_ + b2i) * STATE_;
            float* o = g_state_out + ((size_t)e * B_ + b2i) * STATE_;
#pragma unroll
            for (int j = 0; j < 4; j++) {
                const float* d = g_legs_diff + ((size_t)e * 4 * B_ + (size_t)j * B_ + b2i) * 4;
                o[13 + 2 * j] = st[13 + 2 * j] + d[0];
                o[14 + 2 * j] = st[14 + 2 * j] + d[2];
                o[21 + 2 * j] = st[21 + 2 * j] + d[1];
                o[22 + 2 * j] = st[22 + 2 * j] + d[3];
            }
        }
    }
}

// =======================================================================
// Kernel: ensemble mean
// =======================================================================
__global__ void mean_kernel(float* __restrict__ out) {
    const size_t n4 = (size_t)B_ * STATE_ / 4;
    const float4* s0 = (const float4*)g_state_out;
    const float4* s1 = (const float4*)(g_state_out + (size_t)1 * B_ * STATE_);
    const float4* s2 = (const float4*)(g_state_out + (size_t)2 * B_ * STATE_);
    const float4* s3 = (const float4*)(g_state_out + (size_t)3 * B_ * STATE_);
    for (size_t i = blockIdx.x * blockDim.x + threadIdx.x; i < n4;
         i += (size_t)gridDim.x * blockDim.x) {
        float4 a = s0[i], b = s1[i], c = s2[i], d = s3[i];
        float4 r;
        r.x = 0.25f * (a.x + b.x + c.x + d.x);
        r.y = 0.25f * (a.y + b.y + c.y + d.y);
        r.z = 0.25f * (a.z + b.z + c.z + d.z);
        r.w = 0.25f * (a.w + b.w + c.w + d.w);
        ((float4*)out)[i] = r;
    }
}

extern "C" void kernel_launch(void* const* d_in, const int* in_sizes, int n_in,
                              void* d_out, int out_size) {
    const float* state       = (const float*)d_in[0];
    const float* act         = (const float*)d_in[1];
    const float* wl0         = (const float*)d_in[2];
    const float* bl0         = (const float*)d_in[3];
    const float* wl1         = (const float*)d_in[4];
    const float* bl1         = (const float*)d_in[5];
    const float* wl2         = (const float*)d_in[6];
    const float* bl2         = (const float*)d_in[7];
    const float* wp0         = (const float*)d_in[8];
    const float* bp0         = (const float*)d_in[9];
    const float* wp1         = (const float*)d_in[10];
    const float* bp1         = (const float*)d_in[11];
    const float* wp2         = (const float*)d_in[12];
    const float* bp2         = (const float*)d_in[13];
    const float* mu_leg      = (const float*)d_in[14];
    const float* sigma_leg   = (const float*)d_in[15];
    const float* mu_pose     = (const float*)d_in[16];
    const float* sigma_pose  = (const float*)d_in[17];
    const float* mu_t_leg    = (const float*)d_in[18];
    const float* sigma_t_leg = (const float*)d_in[19];
    const float* mu_t_pose   = (const float*)d_in[20];
    const float* sigma_t_pose= (const float*)d_in[21];

    const int smem = SMEM_FLOATS * (int)sizeof(float);   // 166912 B
    cudaFuncSetAttribute(mlp_kernel<0>, cudaFuncAttributeMaxDynamicSharedMemorySize, smem);
    cudaFuncSetAttribute(mlp_kernel<1>, cudaFuncAttributeMaxDynamicSharedMemorySize, smem);

    // 1) pack W1 fragments (bf16 hi/lo)
    prep_kernel<<<2048, 256>>>(wl1, wp1);

    // 2) leg net: (E, 4B) rows -> g_legs_diff
    mlp_kernel<0><<<dim3(2048, E_), 256, smem>>>(state, act, wl0, bl0, bl1, wl2, bl2,
                                                 mu_leg, sigma_leg, mu_t_leg, sigma_t_leg);

    // 3) pose net: (E, B) rows -> g_state_out
    mlp_kernel<1><<<dim3(512, E_), 256, smem>>>(state, nullptr, wp0, bp0, bp1, wp2, bp2,
                                                mu_pose, sigma_pose, mu_t_pose, sigma_t_pose);

    // 4) ensemble mean
    mean_kernel<<<256, 256>>>((float*)d_out);
}

// round 13
// speedup vs baseline: 2.7005x; 1.2301x over previous
#include <cuda_runtime.h>
#include <cuda_bf16.h>
#include <cstdint>

// Problem constants
#define E_      4
#define B_      16384
#define STATE_  29
#define HID_    512

// ---------------- SMEM layout (float offsets), TM=64 rows/CTA ----------------
// A fragments: 32 kc x 4 mtiles x 32 lanes x 4 regs (u32) = 16384 u32 each
#define OFF_AH  0
#define OFF_AL  16384
#define OFF_XS  32768     // 64 x 33 (padded)  = 2112
#define OFF_W0  34880     // W0 [IN x 512]     (<=14848)
#define OFF_B0  49728     // 512
#define OFF_B1  50240     // 512
#define OFF_W2  50752     // 512 x NO (<=6656)
#define SMEM_FLOATS 57408 // 229632 bytes
#define HROW 520          // Hs overlays [0, 33280) after mainloop (A frags dead)
#define XROW 33

// ---------------- device scratch ----------------
// Pre-packed W1 fragments: per (net,e): 64 ntiles x 32 kc x 32 lanes x {b0h,b1h,b0l,b1l}
__device__ uint32_t g_B[2][(size_t)E_ * 262144];              // 8 MB total
__device__ float g_legs_diff[(size_t)E_ * 4 * B_ * 4];        // (E, 4, B, 4)
__device__ float g_state_out[(size_t)E_ * B_ * STATE_];       // (E, B, 29)

// ---------------- helpers ----------------
__device__ __forceinline__ uint32_t packbf(float x, float y) {
    __nv_bfloat162 h = __floats2bfloat162_rn(x, y);   // .x = low 16 bits
    return *reinterpret_cast<uint32_t*>(&h);
}
__device__ __forceinline__ float bfhi(float x) {
    return __bfloat162float(__float2bfloat16_rn(x));
}
// mma.sync m16n8k16 row.col f32.bf16.bf16.f32 (standard PTX, sm_80+)
__device__ __forceinline__ void mma16816(float* d, uint4 a, uint32_t b0, uint32_t b1) {
    asm volatile(
        "mma.sync.aligned.m16n8k16.row.col.f32.bf16.bf16.f32 "
        "{%0,%1,%2,%3}, {%4,%5,%6,%7}, {%8,%9}, {%0,%1,%2,%3};"
        : "+f"(d[0]), "+f"(d[1]), "+f"(d[2]), "+f"(d[3])
        : "r"(a.x), "r"(a.y), "r"(a.z), "r"(a.w), "r"(b0), "r"(b1));
}

// =======================================================================
// Prep: split W1 into bf16 hi/lo, pack in mma B-fragment register order.
// Per (nt, kc, lane): [b0h, b1h, b0l, b1l] -> one LDG.128 per consumer.
// =======================================================================
__global__ void prep_kernel(const float* __restrict__ wl1, const float* __restrict__ wp1) {
    int idx = blockIdx.x * 256 + threadIdx.x;      // 524288 total
    int l   = idx & 31;
    int kc  = (idx >> 5) & 31;
    int nt  = (idx >> 10) & 63;
    int e   = (idx >> 16) & 3;
    int net = idx >> 18;
    const float* W = (net ? wp1 : wl1) + (size_t)e * 512 * 512;   // [k][n]
    int g = l >> 2, c = l & 3;
    int n  = nt * 8 + g;
    int k0 = kc * 16 + 2 * c;
    float w00 = W[(size_t)k0 * 512 + n];
    float w01 = W[(size_t)(k0 + 1) * 512 + n];
    float w10 = W[(size_t)(k0 + 8) * 512 + n];
    float w11 = W[(size_t)(k0 + 9) * 512 + n];
    float h00 = bfhi(w00), h01 = bfhi(w01), h10 = bfhi(w10), h11 = bfhi(w11);
    uint32_t* dst = g_B[net] + (size_t)e * 262144 + ((size_t)(nt * 32 + kc) * 32 + l) * 4;
    dst[0] = packbf(w00, w01);
    dst[1] = packbf(w10, w11);
    dst[2] = packbf(w00 - h00, w01 - h01);
    dst[3] = packbf(w10 - h10, w11 - h11);
}

// =======================================================================
// Fused MLP, TM=64 rows per CTA, 256 threads (8 warps).
// layer0 (FFMA -> A frags SMEM) -> layer1 (mma.sync 3x bf16 split,
// acc[4][8][4] in regs) -> relu+b1 -> Hs (overlay) -> layer2 (FFMA).
// Warp w owns n-cols w*64..w*64+63 for all 64 rows.
// =======================================================================
template <int NET>
__global__ void __launch_bounds__(256, 1)
mlp_kernel(const float* __restrict__ state, const float* __restrict__ act,
           const float* __restrict__ w0, const float* __restrict__ b0v,
           const float* __restrict__ b1v, const float* __restrict__ w2,
           const float* __restrict__ b2v, const float* __restrict__ mu,
           const float* __restrict__ sigma, const float* __restrict__ mu_t,
           const float* __restrict__ sigma_t) {
    constexpr int IN = NET ? 29 : 6;
    constexpr int NO = NET ? 13 : 4;
    extern __shared__ float smem[];
    uint32_t* AH = (uint32_t*)(smem + OFF_AH);
    uint32_t* AL = (uint32_t*)(smem + OFF_AL);
    float* Hs  = smem;                 // overlay, used after mainloop only
    float* Xs  = smem + OFF_XS;
    float* W0s = smem + OFF_W0;
    float* B0s = smem + OFF_B0;
    float* B1s = smem + OFF_B1;
    float* W2s = smem + OFF_W2;

    const int t = threadIdx.x, lane = t & 31, wid = t >> 5;
    const int e = blockIdx.y;
    const int row0 = blockIdx.x * 64;

    // ---- stage normalized inputs Xs [64 x 33] ----
    for (int q = t; q < 64 * IN; q += 256) {
        int r = q / IN, i = q % IN;
        float v;
        if (NET == 0) {
            int grow = row0 + r, j = grow >> 14, bb = grow & (B_ - 1);
            const float* st = state + ((size_t)e * B_ + bb) * STATE_;
            const float* ac = act + ((size_t)e * B_ + bb) * 8;
            if (i == 0)      v = st[13 + 2 * j];
            else if (i == 1) v = st[21 + 2 * j];
            else if (i == 2) v = st[14 + 2 * j];
            else if (i == 3) v = st[22 + 2 * j];
            else if (i == 4) v = ac[2 * j];
            else             v = ac[2 * j + 1];
        } else {
            int bb = row0 + r;
            if (i < 13) v = state[((size_t)e * B_ + bb) * STATE_ + i];
            else {
                int m = i - 13, j, comp;
                if (m < 8) { j = m >> 1; comp = (m & 1) ? 2 : 0; }
                else       { int m2 = m - 8; j = m2 >> 1; comp = (m2 & 1) ? 3 : 1; }
                v = g_legs_diff[((size_t)e * 4 * B_ + (size_t)j * B_ + bb) * 4 + comp];
            }
        }
        Xs[r * XROW + i] = (v - mu[i]) / (sigma[i] + 1e-8f);
    }
    // ---- stage W0 [IN x 512], biases, packed W2 ----
    for (int q = t; q < IN * 512; q += 256) W0s[q] = w0[(size_t)e * IN * 512 + q];
    for (int q = t; q < 512; q += 256) {
        B0s[q] = b0v[(size_t)e * 512 + q];
        B1s[q] = b1v[(size_t)e * 512 + q];
    }
    if (NET == 0) {
        for (int q = t; q < 512 * 4; q += 256) {
            int k = q >> 2, o = q & 3;
            W2s[q] = w2[((size_t)e * 512 + k) * 8 + o];
        }
    } else {
        for (int q = t; q < 512 * 13; q += 256) {
            int k = q / 13, o = q % 13;
            W2s[q] = w2[((size_t)e * 512 + k) * 26 + o];
        }
    }
    __syncthreads();

    // ---- layer0: H[row][k] = relu(X*W0 + b0) written as A fragments ----
    // thread: row = t & 63, col-phase q = t >> 6 (cols p*8 + 2q, p=0..63)
    {
        const int row = t & 63;
        const int q = t >> 6;
        const int mt = row >> 4, rr = row & 15;
        const int g = rr & 7, rh = rr >> 3;
        float xv[IN];
#pragma unroll
        for (int i = 0; i < IN; i++) xv[i] = Xs[row * XROW + i];
#pragma unroll 4
        for (int p = 0; p < 64; p++) {
            const int col0 = p * 8 + 2 * q;
            const int kc = col0 >> 4;
            const int kh = (col0 >> 3) & 1;
            float h0 = B0s[col0], h1 = B0s[col0 + 1];
#pragma unroll
            for (int i = 0; i < IN; i++) {
                h0 += xv[i] * W0s[i * 512 + col0];
                h1 += xv[i] * W0s[i * 512 + col0 + 1];
            }
            h0 = fmaxf(h0, 0.f);
            h1 = fmaxf(h1, 0.f);
            float h0h = bfhi(h0), h1h = bfhi(h1);
            const int addr = kc * 512 + mt * 128 + (g * 4 + q) * 4 + kh * 2 + rh;
            AH[addr] = packbf(h0, h1);
            AL[addr] = packbf(h0 - h0h, h1 - h1h);
        }
    }
    __syncthreads();

    // ---- layer1: [64 x 512] = A * W1, 3x bf16 split ----
    float acc[4][8][4];
#pragma unroll
    for (int m = 0; m < 4; m++)
#pragma unroll
        for (int n = 0; n < 8; n++)
#pragma unroll
            for (int j = 0; j < 4; j++) acc[m][n][j] = 0.f;

    const uint4* Bp = (const uint4*)(g_B[NET] + (size_t)e * 262144) + (size_t)wid * 8 * 32 * 32;
    for (int kc = 0; kc < 32; kc++) {
        uint4 ah[4], al[4];
#pragma unroll
        for (int mt = 0; mt < 4; mt++) {
            ah[mt] = ((const uint4*)(AH + kc * 512 + mt * 128))[lane];
            al[mt] = ((const uint4*)(AL + kc * 512 + mt * 128))[lane];
        }
#pragma unroll
        for (int ntl = 0; ntl < 8; ntl++) {
            uint4 vb = Bp[(ntl * 32 + kc) * 32 + lane];
#pragma unroll
            for (int mt = 0; mt < 4; mt++) mma16816(acc[mt][ntl], ah[mt], vb.x, vb.y);
#pragma unroll
            for (int mt = 0; mt < 4; mt++) mma16816(acc[mt][ntl], ah[mt], vb.z, vb.w);
#pragma unroll
            for (int mt = 0; mt < 4; mt++) mma16816(acc[mt][ntl], al[mt], vb.x, vb.y);
        }
    }
    __syncthreads();   // A frags dead; Hs overlay becomes safe

    // ---- epilogue: relu(D + b1) -> Hs ----
    {
        const int g = lane >> 2, c = lane & 3;
#pragma unroll
        for (int mt = 0; mt < 4; mt++) {
#pragma unroll
            for (int ntl = 0; ntl < 8; ntl++) {
                const int col = wid * 64 + ntl * 8 + 2 * c;
                const int r1 = mt * 16 + g, r2 = r1 + 8;
                float b0c = B1s[col], b1c = B1s[col + 1];
                float2 v1 = make_float2(fmaxf(acc[mt][ntl][0] + b0c, 0.f),
                                        fmaxf(acc[mt][ntl][1] + b1c, 0.f));
                float2 v2 = make_float2(fmaxf(acc[mt][ntl][2] + b0c, 0.f),
                                        fmaxf(acc[mt][ntl][3] + b1c, 0.f));
                *(float2*)&Hs[r1 * HROW + col] = v1;
                *(float2*)&Hs[r2 * HROW + col] = v2;
            }
        }
    }
    __syncthreads();

    // ---- layer2 + outputs ----
    if (NET == 0) {
        const int row = t >> 2, o = t & 3;
        float s = 0.f;
#pragma unroll 8
        for (int k = 0; k < 512; k++) s += Hs[row * HROW + k] * W2s[k * 4 + o];
        float v = s + b2v[(size_t)e * 8 + o];
        g_legs_diff[((size_t)e * 4 * B_ + row0 + row) * 4 + o] =
            v * (sigma_t[o] + 1e-8f) + mu_t[o];
    } else {
        const int row = t >> 2, q = t & 3;
        const int bb = row0 + row;
        float s[4];
        int no = 0;
        int ols[4];
        for (int o = q; o < 13; o += 4) ols[no++] = o;
#pragma unroll
        for (int m = 0; m < 4; m++) s[m] = 0.f;
#pragma unroll 4
        for (int k = 0; k < 512; k++) {
            float h = Hs[row * HROW + k];
#pragma unroll
            for (int m = 0; m < 4; m++)
                if (m < no) s[m] += h * W2s[k * 13 + ols[m]];
        }
        const float* st = state + ((size_t)e * B_ + bb) * STATE_;
        float* o = g_state_out + ((size_t)e * B_ + bb) * STATE_;
#pragma unroll
        for (int m = 0; m < 4; m++) {
            if (m < no) {
                int c = ols[m];
                float v = s[m] + b2v[(size_t)e * 26 + c];
                o[c] = v * (sigma_t[c] + 1e-8f) + mu_t[c] + st[c];
            }
        }
        // leg part of next_state (cols 13..28)
        if (t < 64) {
            int b2i = row0 + t;
            const float* st2 = state + ((size_t)e * B_ + b2i) * STATE_;
            float* o2 = g_state_out + ((size_t)e * B_ + b2i) * STATE_;
#pragma unroll
            for (int j = 0; j < 4; j++) {
                const float* d = g_legs_diff + ((size_t)e * 4 * B_ + (size_t)j * B_ + b2i) * 4;
                o2[13 + 2 * j] = st2[13 + 2 * j] + d[0];
                o2[14 + 2 * j] = st2[14 + 2 * j] + d[2];
                o2[21 + 2 * j] = st2[21 + 2 * j] + d[1];
                o2[22 + 2 * j] = st2[22 + 2 * j] + d[3];
            }
        }
    }
}

// =======================================================================
// Kernel: ensemble mean
// =======================================================================
__global__ void mean_kernel(float* __restrict__ out) {
    const size_t n4 = (size_t)B_ * STATE_ / 4;
    const float4* s0 = (const float4*)g_state_out;
    const float4* s1 = (const float4*)(g_state_out + (size_t)1 * B_ * STATE_);
    const float4* s2 = (const float4*)(g_state_out + (size_t)2 * B_ * STATE_);
    const float4* s3 = (const float4*)(g_state_out + (size_t)3 * B_ * STATE_);
    for (size_t i = blockIdx.x * blockDim.x + threadIdx.x; i < n4;
         i += (size_t)gridDim.x * blockDim.x) {
        float4 a = s0[i], b = s1[i], c = s2[i], d = s3[i];
        float4 r;
        r.x = 0.25f * (a.x + b.x + c.x + d.x);
        r.y = 0.25f * (a.y + b.y + c.y + d.y);
        r.z = 0.25f * (a.z + b.z + c.z + d.z);
        r.w = 0.25f * (a.w + b.w + c.w + d.w);
        ((float4*)out)[i] = r;
    }
}

extern "C" void kernel_launch(void* const* d_in, const int* in_sizes, int n_in,
                              void* d_out, int out_size) {
    const float* state       = (const float*)d_in[0];
    const float* act         = (const float*)d_in[1];
    const float* wl0         = (const float*)d_in[2];
    const float* bl0         = (const float*)d_in[3];
    const float* wl1         = (const float*)d_in[4];
    const float* bl1         = (const float*)d_in[5];
    const float* wl2         = (const float*)d_in[6];
    const float* bl2         = (const float*)d_in[7];
    const float* wp0         = (const float*)d_in[8];
    const float* bp0         = (const float*)d_in[9];
    const float* wp1         = (const float*)d_in[10];
    const float* bp1         = (const float*)d_in[11];
    const float* wp2         = (const float*)d_in[12];
    const float* bp2         = (const float*)d_in[13];
    const float* mu_leg      = (const float*)d_in[14];
    const float* sigma_leg   = (const float*)d_in[15];
    const float* mu_pose     = (const float*)d_in[16];
    const float* sigma_pose  = (const float*)d_in[17];
    const float* mu_t_leg    = (const float*)d_in[18];
    const float* sigma_t_leg = (const float*)d_in[19];
    const float* mu_t_pose   = (const float*)d_in[20];
    const float* sigma_t_pose= (const float*)d_in[21];

    const int smem = SMEM_FLOATS * (int)sizeof(float);   // 229632 B
    cudaFuncSetAttribute(mlp_kernel<0>, cudaFuncAttributeMaxDynamicSharedMemorySize, smem);
    cudaFuncSetAttribute(mlp_kernel<1>, cudaFuncAttributeMaxDynamicSharedMemorySize, smem);

    // 1) pack W1 fragments (bf16 hi/lo)
    prep_kernel<<<2048, 256>>>(wl1, wp1);

    // 2) leg net: (E, 4B) rows -> g_legs_diff
    mlp_kernel<0><<<dim3(1024, E_), 256, smem>>>(state, act, wl0, bl0, bl1, wl2, bl2,
                                                 mu_leg, sigma_leg, mu_t_leg, sigma_t_leg);

    // 3) pose net: (E, B) rows -> g_state_out
    mlp_kernel<1><<<dim3(256, E_), 256, smem>>>(state, nullptr, wp0, bp0, bp1, wp2, bp2,
                                                mu_pose, sigma_pose, mu_t_pose, sigma_t_pose);

    // 4) ensemble mean
    mean_kernel<<<256, 256>>>((float*)d_out);
}